// round 2
// baseline (speedup 1.0000x reference)
#include <cuda_runtime.h>
#include <cuda_bf16.h>

#define TOKENS 16384
#define HIDDEN 2048
#define NEXP   128
#define NOUT   256   // 0..127 = original router, 128..255 = bvh router
#define TOPK   8
#define NCAND  32

#define BM 64
#define BK 16

// Scratch (no allocations allowed): transposed weights + fused logits
__device__ float g_wT[HIDDEN * NOUT];      // [h][n]  (2 MB)
__device__ float g_logits[TOKENS * NOUT];  // [t][n]  (16 MB)

// ---------------------------------------------------------------------------
// Kernel 0: transpose both routers' weights into [H][256] for coalesced loads
// ---------------------------------------------------------------------------
__global__ void wtrans_kernel(const float* __restrict__ wo,
                              const float* __restrict__ wb) {
    int idx = blockIdx.x * blockDim.x + threadIdx.x;
    if (idx >= HIDDEN * NOUT) return;
    int h = idx / NOUT;
    int n = idx - h * NOUT;
    float v = (n < NEXP) ? wo[n * HIDDEN + h] : wb[(n - NEXP) * HIDDEN + h];
    g_wT[idx] = v;
}

// ---------------------------------------------------------------------------
// Kernel 1: fp32 GEMM  logits[t][n] = sum_h x[t][h] * wT[h][n]
// Block: 64 tokens x 256 outputs, 256 threads, 8x8 microtile, BK=16.
// Accuracy: per-BK block partial (ascending fmaf) + Kahan-compensated merge.
// ---------------------------------------------------------------------------
__global__ __launch_bounds__(256) void gemm_kernel(const float* __restrict__ x) {
    __shared__ float xs[BM][BK];     // 64 x 16  (4 KB)
    __shared__ float ws[BK][NOUT];   // 16 x 256 (16 KB)

    const int tid = threadIdx.x;
    const int m0  = blockIdx.x * BM;
    const int tx  = tid & 31;   // output-col group (8 cols each)
    const int ty  = tid >> 5;   // token group (8 tokens each)

    float acc[8][8];   // Kahan sum
    float cmp[8][8];   // Kahan compensation
#pragma unroll
    for (int i = 0; i < 8; ++i)
#pragma unroll
        for (int j = 0; j < 8; ++j) { acc[i][j] = 0.f; cmp[i][j] = 0.f; }

    const int xr = tid >> 2;          // 0..63 token row for x-tile load
    const int xk = (tid & 3) << 2;    // 0,4,8,12

    for (int k0 = 0; k0 < HIDDEN; k0 += BK) {
        float4 xv = *(const float4*)&x[(size_t)(m0 + xr) * HIDDEN + k0 + xk];
        *(float4*)&xs[xr][xk] = xv;
#pragma unroll
        for (int i = 0; i < 4; ++i) {
            int f4 = tid + i * 256;
            int kk = f4 >> 6;            // 0..15
            int c4 = (f4 & 63) << 2;     // 0..252
            *(float4*)&ws[kk][c4] = *(const float4*)&g_wT[(size_t)(k0 + kk) * NOUT + c4];
        }
        __syncthreads();

        float bp[8][8];   // fresh block partial
#pragma unroll
        for (int i = 0; i < 8; ++i)
#pragma unroll
            for (int j = 0; j < 8; ++j) bp[i][j] = 0.f;

#pragma unroll
        for (int k = 0; k < BK; ++k) {
            float xf[8], wf[8];
#pragma unroll
            for (int i = 0; i < 8; ++i) xf[i] = xs[ty * 8 + i][k];  // uniform per warp
            float4 w0 = *(const float4*)&ws[k][tx * 8];
            float4 w1 = *(const float4*)&ws[k][tx * 8 + 4];
            wf[0] = w0.x; wf[1] = w0.y; wf[2] = w0.z; wf[3] = w0.w;
            wf[4] = w1.x; wf[5] = w1.y; wf[6] = w1.z; wf[7] = w1.w;
#pragma unroll
            for (int i = 0; i < 8; ++i)
#pragma unroll
                for (int j = 0; j < 8; ++j)
                    bp[i][j] = fmaf(xf[i], wf[j], bp[i][j]);
        }

        // Kahan merge: acc += bp (compensated; no muls -> no fma contraction risk)
#pragma unroll
        for (int i = 0; i < 8; ++i)
#pragma unroll
            for (int j = 0; j < 8; ++j) {
                float y = bp[i][j] - cmp[i][j];
                float t = acc[i][j] + y;
                cmp[i][j] = (t - acc[i][j]) - y;
                acc[i][j] = t;
            }
        __syncthreads();
    }

#pragma unroll
    for (int i = 0; i < 8; ++i) {
        size_t row = (size_t)(m0 + ty * 8 + i) * NOUT + tx * 8;
        *(float4*)&g_logits[row]     = make_float4(acc[i][0], acc[i][1], acc[i][2], acc[i][3]);
        *(float4*)&g_logits[row + 4] = make_float4(acc[i][4], acc[i][5], acc[i][6], acc[i][7]);
    }
}

// ---------------------------------------------------------------------------
// Precise fp32 exp (immune to --use_fast_math): Cody-Waite + deg-6 Taylor.
// Valid for x <= 0 (softmax-shifted), |x| < 88. Error ~1 ulp.
// ---------------------------------------------------------------------------
__device__ __forceinline__ float exp_precise(float xx) {
    float kf = rintf(xx * 1.4426950408889634f);
    float r  = fmaf(kf, -0.693145751953125f, xx);      // ln2_hi (exact in fp32)
    r = fmaf(kf, -1.42860676533018704e-06f, r);        // ln2_lo
    // e^r, r in [-0.347, 0.347], Horner with fused ops
    float p = 1.98412698412698413e-04f;                // 1/5040
    p = fmaf(p, r, 1.38888888888888889e-03f);          // 1/720
    p = fmaf(p, r, 8.33333333333333333e-03f);          // 1/120
    p = fmaf(p, r, 4.16666666666666667e-02f);          // 1/24
    p = fmaf(p, r, 1.66666666666666667e-01f);          // 1/6
    p = fmaf(p, r, 0.5f);
    p = fmaf(p, r, 1.0f);
    p = fmaf(p, r, 1.0f);                              // wait-free: p = 1 + r + r^2*(...)
    // NOTE: the two trailing fmaf(p,r,1) implement 1 + r*(1 + r*(1/2 + ...)) exactly
    int ki = (int)kf;
    float scale = __int_as_float((ki + 127) << 23);    // exact 2^k (k >= -126 here)
    return p * scale;
}

// ---------------------------------------------------------------------------
// Kernel 2: per-token routing. 1 block (128 threads) per token.
// ---------------------------------------------------------------------------
__device__ __forceinline__ float warpMax(float v) {
#pragma unroll
    for (int o = 16; o; o >>= 1) v = fmaxf(v, __shfl_xor_sync(0xffffffffu, v, o));
    return v;
}
__device__ __forceinline__ float warpSum(float v) {
#pragma unroll
    for (int o = 16; o; o >>= 1) v += __shfl_xor_sync(0xffffffffu, v, o);
    return v;
}

__global__ __launch_bounds__(128) void route_kernel(float* __restrict__ out) {
    const int t = blockIdx.x;
    const int e = threadIdx.x;
    const int wid = e >> 5;
    const int lane = e & 31;

    __shared__ float s4[4];
    __shared__ float sb[NEXP];       // bvh probs
    __shared__ float cand_p[NCAND];
    __shared__ int   cand_e[NCAND];
    __shared__ float top_p[TOPK];
    __shared__ int   top_e[TOPK];

    float fl = g_logits[(size_t)t * NOUT + e];
    float bl = g_logits[(size_t)t * NOUT + NEXP + e];

    // ---- full softmax ----
    float wm = warpMax(fl);
    if (lane == 0) s4[wid] = wm;
    __syncthreads();
    float m1 = fmaxf(fmaxf(s4[0], s4[1]), fmaxf(s4[2], s4[3]));
    __syncthreads();
    float p = exp_precise(fl - m1);
    float wsum = warpSum(p);
    if (lane == 0) s4[wid] = wsum;
    __syncthreads();
    float s1 = s4[0] + s4[1] + s4[2] + s4[3];
    __syncthreads();
    float prob = __fdiv_rn(p, s1);
    out[(size_t)t * NEXP + e] = prob;

    // ---- bvh softmax ----
    wm = warpMax(bl);
    if (lane == 0) s4[wid] = wm;
    __syncthreads();
    float m2 = fmaxf(fmaxf(s4[0], s4[1]), fmaxf(s4[2], s4[3]));
    __syncthreads();
    float q = exp_precise(bl - m2);
    wsum = warpSum(q);
    if (lane == 0) s4[wid] = wsum;
    __syncthreads();
    float s2 = s4[0] + s4[1] + s4[2] + s4[3];
    float bprob = __fdiv_rn(q, s2);
    sb[e] = bprob;
    __syncthreads();

    // ---- rank by bvh prob (descending, ties -> lower index, as lax.top_k) ----
    int r = 0;
#pragma unroll 8
    for (int j = 0; j < NEXP; ++j) {
        float v = sb[j];
        r += (v > bprob) || (v == bprob && j < e);
    }
    if (r < NCAND) { cand_e[r] = e; cand_p[r] = prob; }
    __syncthreads();

    // ---- top-8 among 32 candidates by full prob (ties -> earlier cand pos) ----
    if (e < NCAND) {
        float cp = cand_p[e];
        int r2 = 0;
#pragma unroll
        for (int j = 0; j < NCAND; ++j) {
            float v = cand_p[j];
            r2 += (v > cp) || (v == cp && j < e);
        }
        if (r2 < TOPK) { top_e[r2] = cand_e[e]; top_p[r2] = cp; }
    }
    __syncthreads();

    // ---- renormalize + write ----
    if (e == 0) {
        float s = 0.f;
#pragma unroll
        for (int k = 0; k < TOPK; ++k) s += top_p[k];
        float* ov = out + (size_t)TOKENS * NEXP + (size_t)t * TOPK;
        float* oi = out + (size_t)TOKENS * NEXP + (size_t)TOKENS * TOPK + (size_t)t * TOPK;
#pragma unroll
        for (int k = 0; k < TOPK; ++k) {
            ov[k] = __fdiv_rn(top_p[k], s);
            oi[k] = (float)top_e[k];
        }
    }
}

// ---------------------------------------------------------------------------
extern "C" void kernel_launch(void* const* d_in, const int* in_sizes, int n_in,
                              void* d_out, int out_size) {
    const float* x  = (const float*)d_in[0];   // [16384, 2048]
    const float* wo = (const float*)d_in[1];   // [128, 2048] original router
    const float* wb = (const float*)d_in[2];   // [128, 2048] bvh router
    float* out = (float*)d_out;

    wtrans_kernel<<<(HIDDEN * NOUT + 255) / 256, 256>>>(wo, wb);
    gemm_kernel<<<TOKENS / BM, 256>>>(x);
    route_kernel<<<TOKENS, 128>>>(out);
}